// round 9
// baseline (speedup 1.0000x reference)
#include <cuda_runtime.h>
#include <cuda_bf16.h>
#include <math.h>
#include <cstdint>

#define Bn 16384
#define Dn 1024
#define Kn 512
#define Ln 128
#define Hn 64

#define MTILE 128            // k-rows per MMA tile (per slice)
#define NTILE 64             // b-cols per CTA
#define NCHUNK 8             // 128-elem fp8 chunks in D
#define NSLICE 4             // k-slices (4 x 128 = 512)
#define NITER  (NSLICE * NCHUNK)   // 32
#define STAGES 3
#define ASTAGE 16384u        // one A stage: 128 rows x 128B

#define CHB_PHI ((uint64_t)Kn * 128)   // 64 KB per chunk block

// smem offsets (128B-aligned base)
#define OFF_BT   0u
#define OFF_AST  65536u
#define OFF_XN   (65536u + STAGES * ASTAGE)          // 114688
#define OFF_CS   (OFF_XN + 256u)
#define SMEM_REQ (OFF_CS + 256u + 128u)

#define L2E 1.4426950408889634f
#define SCALE 16.0f
#define SINV (2.0f * L2E / (SCALE * SCALE))

// ---------------- scratch ----------------
__device__ uint8_t g_phi8[Kn * Dn];   // chunk-major, pre-swizzled
__device__ float g_phinorm[Kn];

// ---------------- helpers ----------------
__device__ __forceinline__ uint32_t smem_u32(const void* p) {
    uint32_t a;
    asm("{ .reg .u64 t; cvta.to.shared.u64 t, %1; cvt.u32.u64 %0, t; }" : "=r"(a) : "l"(p));
    return a;
}

#define LDSM4(r0, r1, r2, r3, addr) \
    asm volatile("ldmatrix.sync.aligned.m8n8.x4.shared.b16 {%0,%1,%2,%3}, [%4];" \
                 : "=r"(r0), "=r"(r1), "=r"(r2), "=r"(r3) : "r"(addr))

#define MMA16832(d, a, b0, b1) \
    asm volatile("mma.sync.aligned.m16n8k32.row.col.f32.e4m3.e4m3.f32 " \
                 "{%0,%1,%2,%3}, {%4,%5,%6,%7}, {%8,%9}, {%0,%1,%2,%3};" \
                 : "+f"((d)[0]), "+f"((d)[1]), "+f"((d)[2]), "+f"((d)[3]) \
                 : "r"((a)[0]), "r"((a)[1]), "r"((a)[2]), "r"((a)[3]), \
                   "r"(b0), "r"(b1))

#define CP16(dst, src) \
    asm volatile("cp.async.cg.shared.global [%0], [%1], 16;" :: "r"(dst), "l"(src))
#define CP_COMMIT()  asm volatile("cp.async.commit_group;" ::: "memory")
#define CP_WAIT(n)   asm volatile("cp.async.wait_group %0;" :: "n"(n) : "memory")

__device__ __forceinline__ uint32_t pack_e4m3x4(float e0, float e1, float e2, float e3) {
    uint16_t lo, hi;
    asm("cvt.rn.satfinite.e4m3x2.f32 %0, %1, %2;" : "=h"(lo) : "f"(e1), "f"(e0));
    asm("cvt.rn.satfinite.e4m3x2.f32 %0, %1, %2;" : "=h"(hi) : "f"(e3), "f"(e2));
    return (uint32_t)lo | ((uint32_t)hi << 16);
}

// fast 2^t, FFMA-only. deg-4 poly on [-0.5, 0.5]
__device__ __forceinline__ float exp2_fast(float t) {
    t = fmaxf(t, -126.0f);
    const int   i = __float2int_rn(t);
    const float f = t - (float)i;
    float p = fmaf(0.0096181291f, f, 0.0555041087f);
    p = fmaf(p, f, 0.2402265069f);
    p = fmaf(p, f, 0.6931471806f);
    p = fmaf(p, f, 1.0f);
    return p * __int_as_float((i + 127) << 23);
}

// ============================================================
// Kernel 1: phi MLP -> chunk-major pre-swizzled fp8 + norms
// ============================================================
__global__ __launch_bounds__(256) void phi_kernel(
    const float* __restrict__ z,  const float* __restrict__ W1,
    const float* __restrict__ b1, const float* __restrict__ W2,
    const float* __restrict__ b2, float* __restrict__ out)
{
    __shared__ float zrow[Ln];
    __shared__ float hidden[Hn];
    __shared__ float red[256];
    const int k = blockIdx.x;
    const int t = threadIdx.x;

    if (k == 0 && t == 0) out[0] = 0.0f;

    if (t < Ln) zrow[t] = z[k * Ln + t];
    __syncthreads();

    if (t < Hn) {
        float acc = b1[t];
        #pragma unroll 8
        for (int l = 0; l < Ln; l++)
            acc = fmaf(zrow[l], W1[l * Hn + t], acc);
        hidden[t] = fmaxf(acc, 0.0f);
    }
    __syncthreads();

    const int d0 = t * 4;
    float4 acc = make_float4(b2[d0], b2[d0 + 1], b2[d0 + 2], b2[d0 + 3]);
    #pragma unroll 8
    for (int h = 0; h < Hn; h++) {
        const float hv = hidden[h];
        const float4 w = *reinterpret_cast<const float4*>(W2 + h * Dn + d0);
        acc.x = fmaf(hv, w.x, acc.x);
        acc.y = fmaf(hv, w.y, acc.y);
        acc.z = fmaf(hv, w.z, acc.z);
        acc.w = fmaf(hv, w.w, acc.w);
    }
    {
        const int chunk = t >> 5;   // d0/128
        const uint32_t rowoff = (((((t >> 2) & 7) ^ (k & 7)) << 4) | ((t & 3) << 2));
        *reinterpret_cast<uint32_t*>(
            g_phi8 + (uint64_t)chunk * CHB_PHI + (uint64_t)k * 128 + rowoff) =
            pack_e4m3x4(acc.x * SCALE, acc.y * SCALE, acc.z * SCALE, acc.w * SCALE);
    }

    red[t] = acc.x * acc.x + acc.y * acc.y + acc.z * acc.z + acc.w * acc.w;
    __syncthreads();
    for (int s = 128; s > 0; s >>= 1) {
        if (t < s) red[t] += red[t + s];
        __syncthreads();
    }
    if (t == 0) g_phinorm[k] = red[0];
}

// ============================================================
// Kernel 2: persistent-B fused kernel.
//   Per CTA: convert 64 x-rows fp32->fp8 into smem B-tile (once),
//   stream phi chunks via 3-stage cp.async, fp8 MMA, per-slice exp
//   epilogue, final log-mean for its own 64 columns.
// ============================================================
__global__ __launch_bounds__(256, 2) void main_kernel(
    const float* __restrict__ x, float* __restrict__ out)
{
    extern __shared__ char smem[];
    const uint32_t Sal = (smem_u32(smem) + 127u) & ~127u;
    const uint32_t Bt  = Sal + OFF_BT;
    const uint32_t Ast = Sal + OFF_AST;
    float* xn_sm = reinterpret_cast<float*>(smem + (Sal - smem_u32(smem)) + OFF_XN);
    float* cs_sm = reinterpret_cast<float*>(smem + (Sal - smem_u32(smem)) + OFF_CS);

    const int t    = threadIdx.x;
    const int lane = t & 31;
    const int wid  = t >> 5;
    const int b_base = blockIdx.x * NTILE;

    const int m_off = (wid & 3) * 32;     // 4-way m partition (within 128)
    const int n_off = (wid >> 2) * 32;    // 2-way n partition (within 64)

    // ---- A prologue: stage chunks g=0,1 while we convert x ----
    const uint8_t* srcA0 = g_phi8 + (uint32_t)t * 64;   // iter g: + (g&7)*CHB_PHI + (g>>3)*16384
    #pragma unroll
    for (int pc = 0; pc < 2; pc++) {
        const uint32_t st = Ast + (uint32_t)pc * ASTAGE;
        const uint8_t* sa = srcA0 + (uint64_t)(pc & 7) * CHB_PHI;  // slice 0
        #pragma unroll
        for (int i = 0; i < 4; i++)
            CP16(st + (uint32_t)t * 64u + i * 16u, sa + i * 16);
        CP_COMMIT();
    }

    // ---- convert phase: 8 rows per pass, warp per row ----
    if (t < NTILE) cs_sm[t] = 0.0f;
    #pragma unroll
    for (int it = 0; it < 8; it++) {
        const int row = it * 8 + wid;
        const float* xr = x + (uint64_t)(b_base + row) * Dn;
        float nrm = 0.0f;
        #pragma unroll
        for (int j = 0; j < 8; j++) {
            const int f = j * 32 + lane;    // float4 index 0..255
            const float4 v = *reinterpret_cast<const float4*>(xr + f * 4);
            const uint32_t off = (uint32_t)row * 1024u + (uint32_t)(f >> 5) * 128u
                               + (uint32_t)((((f >> 2) & 7) ^ (row & 7)) << 4)
                               + (uint32_t)((f & 3) << 2);
            uint32_t pk = pack_e4m3x4(v.x * SCALE, v.y * SCALE, v.z * SCALE, v.w * SCALE);
            asm volatile("st.shared.b32 [%0], %1;" :: "r"(Bt + off), "r"(pk));
            nrm = fmaf(v.x, v.x, nrm);
            nrm = fmaf(v.y, v.y, nrm);
            nrm = fmaf(v.z, v.z, nrm);
            nrm = fmaf(v.w, v.w, nrm);
        }
        #pragma unroll
        for (int off = 16; off > 0; off >>= 1)
            nrm += __shfl_xor_sync(0xffffffffu, nrm, off);
        if (lane == 0) xn_sm[row] = nrm;
    }

    // ---- loop-invariant LDSM base offsets ----
    uint32_t a_base[2], b_base2[2];
    {
        const int hi = lane >> 4;
        #pragma unroll
        for (int im = 0; im < 2; im++) {
            const int arow = m_off + im * 16 + (lane & 15);
            const int r = arow & 7;
            a_base[im] = (uint32_t)(arow * 128 + ((hi ^ (r & 1)) << 4) + ((r & 6) << 4));
        }
        const int g  = lane >> 3;
        const int rb = lane & 7;
        #pragma unroll
        for (int in_ = 0; in_ < 2; in_++) {
            const int nrow = n_off + in_ * 16 + ((g >> 1) << 3) + rb;
            b_base2[in_] = (uint32_t)(nrow * 1024 + (((g & 1) ^ (rb & 1)) << 4) + ((rb & 6) << 4));
        }
    }

    float acc[2][4][4];
    #pragma unroll
    for (int i = 0; i < 2; i++)
        #pragma unroll
        for (int j = 0; j < 4; j++)
            #pragma unroll
            for (int r = 0; r < 4; r++) acc[i][j][r] = 0.0f;

    float sn[4][2];
    #pragma unroll
    for (int ing = 0; ing < 4; ing++) { sn[ing][0] = 0.0f; sn[ing][1] = 0.0f; }

    __syncthreads();   // B-tile + xnorms ready

    float xnv[4][2];
    #pragma unroll
    for (int ing = 0; ing < 4; ing++)
        #pragma unroll
        for (int j = 0; j < 2; j++)
            xnv[ing][j] = xn_sm[n_off + ing * 8 + (lane & 3) * 2 + j] * L2E;

    // ---- main loop: 32 iterations (4 slices x 8 chunks) ----
    for (int g = 0; g < NITER; g++) {
        if (g < NITER - 1) CP_WAIT(1); else CP_WAIT(0);
        __syncthreads();

        if (g + 2 < NITER) {
            const int gn = g + 2;
            const uint32_t st = Ast + (uint32_t)(gn % STAGES) * ASTAGE;
            const uint8_t* sa = srcA0 + (uint64_t)(gn & 7) * CHB_PHI
                                      + (uint64_t)(gn >> 3) * (MTILE * 128);
            #pragma unroll
            for (int i = 0; i < 4; i++)
                CP16(st + (uint32_t)t * 64u + i * 16u, sa + i * 16);
            CP_COMMIT();
        }

        const uint32_t As = Ast + (uint32_t)(g % STAGES) * ASTAGE;
        const uint32_t Bc = Bt + (uint32_t)(g & 7) * 128u;
        uint32_t aaddr[2], baddr[2];
        #pragma unroll
        for (int im = 0; im < 2; im++) aaddr[im] = As + a_base[im];
        #pragma unroll
        for (int in_ = 0; in_ < 2; in_++) baddr[in_] = Bc + b_base2[in_];

        #pragma unroll
        for (int ks = 0; ks < 4; ks++) {
            const uint32_t kx = (uint32_t)ks << 5;
            uint32_t a[2][4];
            #pragma unroll
            for (int im = 0; im < 2; im++)
                LDSM4(a[im][0], a[im][1], a[im][2], a[im][3], aaddr[im] ^ kx);
            uint32_t b[8];
            #pragma unroll
            for (int in_ = 0; in_ < 2; in_++)
                LDSM4(b[in_ * 4 + 0], b[in_ * 4 + 1], b[in_ * 4 + 2], b[in_ * 4 + 3],
                      baddr[in_] ^ kx);
            #pragma unroll
            for (int im = 0; im < 2; im++)
                #pragma unroll
                for (int ing = 0; ing < 4; ing++)
                    MMA16832(acc[im][ing], a[im], b[ing * 2], b[ing * 2 + 1]);
        }

        // ---- per-slice epilogue ----
        if ((g & 7) == 7) {
            const int k_base = (g >> 3) * MTILE;
            float pnl[2], pnh[2];
            #pragma unroll
            for (int im = 0; im < 2; im++) {
                pnl[im] = g_phinorm[k_base + m_off + im * 16 + (lane >> 2)] * L2E;
                pnh[im] = g_phinorm[k_base + m_off + im * 16 + (lane >> 2) + 8] * L2E;
            }
            #pragma unroll
            for (int im = 0; im < 2; im++) {
                #pragma unroll
                for (int ing = 0; ing < 4; ing++) {
                    #pragma unroll
                    for (int j = 0; j < 2; j++) {
                        sn[ing][j] += exp2_fast(fmaf(SINV, acc[im][ing][j],     -(pnl[im] + xnv[ing][j])));
                        sn[ing][j] += exp2_fast(fmaf(SINV, acc[im][ing][2 + j], -(pnh[im] + xnv[ing][j])));
                        acc[im][ing][j] = 0.0f;
                        acc[im][ing][2 + j] = 0.0f;
                    }
                }
            }
        }
    }

    // ---- reduce over m-lane groups, then across the 4 m-warps ----
    #pragma unroll
    for (int off = 4; off < 32; off <<= 1)
        #pragma unroll
        for (int ing = 0; ing < 4; ing++)
            #pragma unroll
            for (int j = 0; j < 2; j++)
                sn[ing][j] += __shfl_xor_sync(0xffffffffu, sn[ing][j], off);

    if (lane < 4) {
        #pragma unroll
        for (int ing = 0; ing < 4; ing++)
            #pragma unroll
            for (int j = 0; j < 2; j++)
                atomicAdd(&cs_sm[n_off + ing * 8 + lane * 2 + j], sn[ing][j]);
    }
    __syncthreads();

    // ---- final: log-mean over this CTA's 64 columns ----
    if (t < NTILE) {
        float s = __logf(cs_sm[t] * (1.0f / (float)Kn) + 1e-9f) * (1.0f / (float)Bn);
        #pragma unroll
        for (int off = 16; off > 0; off >>= 1)
            s += __shfl_xor_sync(0xffffffffu, s, off);
        if (lane == 0) atomicAdd(out, s);
    }
}

// ============================================================
extern "C" void kernel_launch(void* const* d_in, const int* in_sizes, int n_in,
                              void* d_out, int out_size)
{
    const float* x  = (const float*)d_in[0];
    const float* z  = (const float*)d_in[1];
    const float* W1 = (const float*)d_in[2];
    const float* b1 = (const float*)d_in[3];
    const float* W2 = (const float*)d_in[4];
    const float* b2 = (const float*)d_in[5];
    float* out = (float*)d_out;

    static int smem_set = 0;
    if (!smem_set) {
        cudaFuncSetAttribute(main_kernel, cudaFuncAttributeMaxDynamicSharedMemorySize,
                             SMEM_REQ);
        smem_set = 1;
    }

    phi_kernel<<<Kn, 256>>>(z, W1, b1, W2, b2, out);
    main_kernel<<<Bn / NTILE, 256, SMEM_REQ>>>(x, out);   // 256 CTAs, single wave
}

// round 10
// speedup vs baseline: 1.0054x; 1.0054x over previous
#include <cuda_runtime.h>
#include <cuda_bf16.h>
#include <math.h>
#include <cstdint>

#define Bn 16384
#define Dn 1024
#define Kn 512
#define Ln 128
#define Hn 64

#define MTILE 128
#define NTILE 128
#define DK    128            // fp8 elems per chunk (128B rows)
#define NCHUNK (Dn / DK)     // 8
#define STAGES 3
#define STAGE_BYTES 32768u   // A(16KB) + B(16KB)

// chunk-major strides (bytes per chunk block)
#define CHB_X   ((uint64_t)Bn * 128)   // 2 MB
#define CHB_PHI ((uint64_t)Kn * 128)   // 64 KB

#define L2E 1.4426950408889634f
#define SCALE 16.0f
#define SINV (2.0f * L2E / (SCALE * SCALE))

// ---------------- scratch (chunk-major, PRE-SWIZZLED) ----------------
__device__ uint8_t g_phi8[Kn * Dn];
__device__ uint8_t g_x8[Bn * Dn];
__device__ float g_phinorm[Kn];
__device__ float g_xnorm[Bn];
__device__ float g_colsum[Bn];
__device__ int   g_cnt[Bn / NTILE];

// ---------------- helpers ----------------
__device__ __forceinline__ uint32_t smem_u32(const void* p) {
    uint32_t a;
    asm("{ .reg .u64 t; cvta.to.shared.u64 t, %1; cvt.u32.u64 %0, t; }" : "=r"(a) : "l"(p));
    return a;
}

#define LDSM4(r0, r1, r2, r3, addr) \
    asm volatile("ldmatrix.sync.aligned.m8n8.x4.shared.b16 {%0,%1,%2,%3}, [%4];" \
                 : "=r"(r0), "=r"(r1), "=r"(r2), "=r"(r3) : "r"(addr))

#define MMA16832(d, a, b0, b1) \
    asm volatile("mma.sync.aligned.m16n8k32.row.col.f32.e4m3.e4m3.f32 " \
                 "{%0,%1,%2,%3}, {%4,%5,%6,%7}, {%8,%9}, {%0,%1,%2,%3};" \
                 : "+f"((d)[0]), "+f"((d)[1]), "+f"((d)[2]), "+f"((d)[3]) \
                 : "r"((a)[0]), "r"((a)[1]), "r"((a)[2]), "r"((a)[3]), \
                   "r"(b0), "r"(b1))

#define CP16(dst, src) \
    asm volatile("cp.async.cg.shared.global [%0], [%1], 16;" :: "r"(dst), "l"(src))
#define CP_COMMIT()  asm volatile("cp.async.commit_group;" ::: "memory")
#define CP_WAIT(n)   asm volatile("cp.async.wait_group %0;" :: "n"(n) : "memory")

__device__ __forceinline__ uint32_t pack_e4m3x4(float e0, float e1, float e2, float e3) {
    uint16_t lo, hi;
    asm("cvt.rn.satfinite.e4m3x2.f32 %0, %1, %2;" : "=h"(lo) : "f"(e1), "f"(e0));
    asm("cvt.rn.satfinite.e4m3x2.f32 %0, %1, %2;" : "=h"(hi) : "f"(e3), "f"(e2));
    return (uint32_t)lo | ((uint32_t)hi << 16);
}

// fast 2^t, FFMA-only. deg-4 poly on [-0.5, 0.5]
__device__ __forceinline__ float exp2_fast(float t) {
    t = fmaxf(t, -126.0f);
    const int   i = __float2int_rn(t);
    const float f = t - (float)i;
    float p = fmaf(0.0096181291f, f, 0.0555041087f);
    p = fmaf(p, f, 0.2402265069f);
    p = fmaf(p, f, 0.6931471806f);
    p = fmaf(p, f, 1.0f);
    return p * __int_as_float((i + 127) << 23);
}

// ============================================================
// Kernel 1 (prep): blocks [0, 2048) = x (warp per row);
//                  blocks [2048, 2048+Kn) = phi MLP
// Both write CHUNK-MAJOR PRE-SWIZZLED fp8.
// ============================================================
__global__ __launch_bounds__(256) void prep_kernel(
    const float* __restrict__ x,  const float* __restrict__ z,
    const float* __restrict__ W1, const float* __restrict__ b1,
    const float* __restrict__ W2, const float* __restrict__ b2,
    float* __restrict__ out)
{
    const int t = threadIdx.x;

    if (blockIdx.x < Bn / 8) {
        const int lane = t & 31;
        const int b = blockIdx.x * 8 + (t >> 5);
        const float* xr = x + (uint64_t)b * Dn;
        const uint32_t rowoff = ((((lane >> 2) ^ (b & 7)) << 4) | ((lane & 3) << 2));
        uint8_t* xo = g_x8 + (uint64_t)b * 128 + rowoff;
        float nrm = 0.0f;
        #pragma unroll
        for (int i = 0; i < 8; i++) {
            const float4 v = *reinterpret_cast<const float4*>(xr + i * 128 + lane * 4);
            *reinterpret_cast<uint32_t*>(xo + i * CHB_X) =
                pack_e4m3x4(v.x * SCALE, v.y * SCALE, v.z * SCALE, v.w * SCALE);
            nrm = fmaf(v.x, v.x, nrm);
            nrm = fmaf(v.y, v.y, nrm);
            nrm = fmaf(v.z, v.z, nrm);
            nrm = fmaf(v.w, v.w, nrm);
        }
        #pragma unroll
        for (int off = 16; off > 0; off >>= 1)
            nrm += __shfl_xor_sync(0xffffffffu, nrm, off);
        if (lane == 0) {
            g_xnorm[b] = nrm;
            g_colsum[b] = 0.0f;
            if (b < Bn / NTILE) g_cnt[b] = 0;
            if (b == 0) out[0] = 0.0f;
        }
    } else {
        __shared__ float zrow[Ln];
        __shared__ float hidden[Hn];
        __shared__ float red[256];
        const int k = blockIdx.x - Bn / 8;

        if (t < Ln) zrow[t] = z[k * Ln + t];
        __syncthreads();

        if (t < Hn) {
            float acc = b1[t];
            #pragma unroll 8
            for (int l = 0; l < Ln; l++)
                acc = fmaf(zrow[l], W1[l * Hn + t], acc);
            hidden[t] = fmaxf(acc, 0.0f);
        }
        __syncthreads();

        const int d0 = t * 4;
        float4 acc = make_float4(b2[d0], b2[d0 + 1], b2[d0 + 2], b2[d0 + 3]);
        #pragma unroll 8
        for (int h = 0; h < Hn; h++) {
            const float hv = hidden[h];
            const float4 w = *reinterpret_cast<const float4*>(W2 + h * Dn + d0);
            acc.x = fmaf(hv, w.x, acc.x);
            acc.y = fmaf(hv, w.y, acc.y);
            acc.z = fmaf(hv, w.z, acc.z);
            acc.w = fmaf(hv, w.w, acc.w);
        }
        {
            const int chunk = t >> 5;
            const uint32_t rowoff = (((((t >> 2) & 7) ^ (k & 7)) << 4) | ((t & 3) << 2));
            *reinterpret_cast<uint32_t*>(
                g_phi8 + (uint64_t)chunk * CHB_PHI + (uint64_t)k * 128 + rowoff) =
                pack_e4m3x4(acc.x * SCALE, acc.y * SCALE, acc.z * SCALE, acc.w * SCALE);
        }

        red[t] = acc.x * acc.x + acc.y * acc.y + acc.z * acc.z + acc.w * acc.w;
        __syncthreads();
        for (int s = 128; s > 0; s >>= 1) {
            if (t < s) red[t] += red[t + s];
            __syncthreads();
        }
        if (t == 0) g_phinorm[k] = red[0];
    }
}

// ============================================================
// Kernel 2 (main): fp8 mma GEMM 128x128, 3-stage cp.async from
//   contiguous pre-swizzled tiles, SW-PIPELINED LDSM, fused exp
// ============================================================
__global__ __launch_bounds__(256, 2) void main_kernel(float* __restrict__ out)
{
    extern __shared__ char smem[];
    uint32_t Sraw = smem_u32(smem);
    const uint32_t Sal = (Sraw + 127u) & ~127u;

    const int t    = threadIdx.x;
    const int lane = t & 31;
    const int wid  = t >> 5;
    const int b_base = blockIdx.x * NTILE;
    const int k_base = blockIdx.y * MTILE;

    const int m_off = (wid & 1) * 64;
    const int n_off = (wid >> 1) * 32;

    const uint8_t* srcA = g_phi8 + (uint64_t)k_base * 128 + (uint32_t)t * 16;
    const uint8_t* srcB = g_x8   + (uint64_t)b_base * 128 + (uint32_t)t * 16;
    const uint32_t doff = (uint32_t)t * 16;

    // ---- loop-invariant LDSM base offsets (within a stage) ----
    uint32_t a_base[4], b_base2[2];
    {
        const int hi = lane >> 4;
        #pragma unroll
        for (int im = 0; im < 4; im++) {
            const int arow = m_off + im * 16 + (lane & 15);
            const int r = arow & 7;
            a_base[im] = (uint32_t)(arow * 128 + ((hi ^ (r & 1)) << 4) + ((r & 6) << 4));
        }
        const int g  = lane >> 3;
        const int rb = lane & 7;
        #pragma unroll
        for (int in_ = 0; in_ < 2; in_++) {
            const int nrow = n_off + in_ * 16 + ((g >> 1) << 3) + rb;
            b_base2[in_] = (uint32_t)(nrow * 128 + (((g & 1) ^ (rb & 1)) << 4) + ((rb & 6) << 4));
        }
    }

    float acc[4][4][4];
    #pragma unroll
    for (int i = 0; i < 4; i++)
        #pragma unroll
        for (int j = 0; j < 4; j++)
            #pragma unroll
            for (int r = 0; r < 4; r++) acc[i][j][r] = 0.0f;

    // prologue: stage chunks 0, 1
    #pragma unroll
    for (int pc = 0; pc < 2; pc++) {
        const uint32_t st = Sal + (uint32_t)pc * STAGE_BYTES;
        const uint8_t* sa = srcA + pc * CHB_PHI;
        const uint8_t* sb = srcB + pc * CHB_X;
        #pragma unroll
        for (int i = 0; i < 4; i++) {
            CP16(st + doff + i * 4096u,          sa + i * 4096);
            CP16(st + 16384u + doff + i * 4096u, sb + i * 4096);
        }
        CP_COMMIT();
    }

    // register double buffers for fragments
    uint32_t af[2][4][4];
    uint32_t bf[2][8];

    for (int c = 0; c < NCHUNK; c++) {
        if (c < NCHUNK - 1) CP_WAIT(1); else CP_WAIT(0);
        __syncthreads();

        if (c + 2 < NCHUNK) {
            const uint32_t st = Sal + (uint32_t)((c + 2) % STAGES) * STAGE_BYTES;
            const uint8_t* sa = srcA + (c + 2) * CHB_PHI;
            const uint8_t* sb = srcB + (uint64_t)(c + 2) * CHB_X;
            #pragma unroll
            for (int i = 0; i < 4; i++) {
                CP16(st + doff + i * 4096u,          sa + i * 4096);
                CP16(st + 16384u + doff + i * 4096u, sb + i * 4096);
            }
            CP_COMMIT();
        }

        const uint32_t As = Sal + (uint32_t)(c % STAGES) * STAGE_BYTES;
        uint32_t aaddr[4], baddr[2];
        #pragma unroll
        for (int im = 0; im < 4; im++) aaddr[im] = As + a_base[im];
        #pragma unroll
        for (int in_ = 0; in_ < 2; in_++) baddr[in_] = As + 16384u + b_base2[in_];

        // preload ks=0 fragments
        #pragma unroll
        for (int im = 0; im < 4; im++)
            LDSM4(af[0][im][0], af[0][im][1], af[0][im][2], af[0][im][3], aaddr[im]);
        #pragma unroll
        for (int in_ = 0; in_ < 2; in_++)
            LDSM4(bf[0][in_ * 4 + 0], bf[0][in_ * 4 + 1], bf[0][in_ * 4 + 2],
                  bf[0][in_ * 4 + 3], baddr[in_]);

        #pragma unroll
        for (int ks = 0; ks < 4; ks++) {
            const int cur = ks & 1;
            if (ks < 3) {
                const uint32_t kx = (uint32_t)(ks + 1) << 5;
                const int nxt = cur ^ 1;
                #pragma unroll
                for (int im = 0; im < 4; im++)
                    LDSM4(af[nxt][im][0], af[nxt][im][1], af[nxt][im][2], af[nxt][im][3],
                          aaddr[im] ^ kx);
                #pragma unroll
                for (int in_ = 0; in_ < 2; in_++)
                    LDSM4(bf[nxt][in_ * 4 + 0], bf[nxt][in_ * 4 + 1], bf[nxt][in_ * 4 + 2],
                          bf[nxt][in_ * 4 + 3], baddr[in_] ^ kx);
            }
            #pragma unroll
            for (int im = 0; im < 4; im++)
                #pragma unroll
                for (int ing = 0; ing < 4; ing++)
                    MMA16832(acc[im][ing], af[cur][im], bf[cur][ing * 2], bf[cur][ing * 2 + 1]);
        }
    }

    // ---------------- fused epilogue ----------------
    float pnl[4], pnh[4];
    #pragma unroll
    for (int im = 0; im < 4; im++) {
        pnl[im] = g_phinorm[k_base + m_off + im * 16 + (lane >> 2)] * L2E;
        pnh[im] = g_phinorm[k_base + m_off + im * 16 + (lane >> 2) + 8] * L2E;
    }
    float xnv[4][2];
    #pragma unroll
    for (int ing = 0; ing < 4; ing++)
        #pragma unroll
        for (int j = 0; j < 2; j++)
            xnv[ing][j] = g_xnorm[b_base + n_off + ing * 8 + (lane & 3) * 2 + j] * L2E;

    float sn[4][2];
    #pragma unroll
    for (int ing = 0; ing < 4; ing++) { sn[ing][0] = 0.0f; sn[ing][1] = 0.0f; }

    #pragma unroll
    for (int im = 0; im < 4; im++) {
        #pragma unroll
        for (int ing = 0; ing < 4; ing++) {
            #pragma unroll
            for (int j = 0; j < 2; j++) {
                sn[ing][j] += exp2_fast(fmaf(SINV, acc[im][ing][j],     -(pnl[im] + xnv[ing][j])));
                sn[ing][j] += exp2_fast(fmaf(SINV, acc[im][ing][2 + j], -(pnh[im] + xnv[ing][j])));
            }
        }
    }
    #pragma unroll
    for (int off = 4; off < 32; off <<= 1)
        #pragma unroll
        for (int ing = 0; ing < 4; ing++)
            #pragma unroll
            for (int j = 0; j < 2; j++)
                sn[ing][j] += __shfl_xor_sync(0xffffffffu, sn[ing][j], off);

    if (lane < 4) {
        #pragma unroll
        for (int ing = 0; ing < 4; ing++)
            #pragma unroll
            for (int j = 0; j < 2; j++)
                atomicAdd(&g_colsum[b_base + n_off + ing * 8 + lane * 2 + j], sn[ing][j]);
    }

    // ---- last CTA of this b-slice finalizes its 128 columns ----
    __shared__ int is_last;
    __threadfence();
    if (t == 0) {
        const int old = atomicAdd(&g_cnt[blockIdx.x], 1);
        is_last = (old == (Kn / MTILE) - 1);
    }
    __syncthreads();
    if (is_last && t < NTILE) {
        float s = __logf(g_colsum[b_base + t] * (1.0f / (float)Kn) + 1e-9f)
                  * (1.0f / (float)Bn);
        #pragma unroll
        for (int off = 16; off > 0; off >>= 1)
            s += __shfl_xor_sync(0xffffffffu, s, off);
        if (lane == 0) atomicAdd(out, s);
    }
}

// ============================================================
extern "C" void kernel_launch(void* const* d_in, const int* in_sizes, int n_in,
                              void* d_out, int out_size)
{
    const float* x  = (const float*)d_in[0];
    const float* z  = (const float*)d_in[1];
    const float* W1 = (const float*)d_in[2];
    const float* b1 = (const float*)d_in[3];
    const float* W2 = (const float*)d_in[4];
    const float* b2 = (const float*)d_in[5];
    float* out = (float*)d_out;

    static int smem_set = 0;
    if (!smem_set) {
        cudaFuncSetAttribute(main_kernel, cudaFuncAttributeMaxDynamicSharedMemorySize,
                             STAGES * STAGE_BYTES + 128);
        smem_set = 1;
    }

    prep_kernel<<<Bn / 8 + Kn, 256>>>(x, z, W1, b1, W2, b2, out);
    dim3 grid(Bn / NTILE, Kn / MTILE);   // (128, 4)
    main_kernel<<<grid, 256, STAGES * STAGE_BYTES + 128>>>(out);
}

// round 11
// speedup vs baseline: 1.0346x; 1.0291x over previous
#include <cuda_runtime.h>
#include <cuda_bf16.h>
#include <math.h>
#include <cstdint>

#define Bn 16384
#define Dn 1024
#define Kn 512
#define Ln 128
#define Hn 64

#define MTILE 128
#define NTILE 128
#define DK    128            // fp8 elems per chunk (128B rows)
#define NCHUNK (Dn / DK)     // 8
#define STAGES 3
#define STAGE_BYTES 32768u   // A(16KB) + B(16KB)

// chunk-major strides (bytes per chunk block)
#define CHB_X   ((uint64_t)Bn * 128)   // 2 MB
#define CHB_PHI ((uint64_t)Kn * 128)   // 64 KB

// smem offsets from 128B-aligned base
#define OFF_MBAR (STAGES * STAGE_BYTES)          // 98304
#define SMEM_REQ (OFF_MBAR + 64 + 128)

#define L2E 1.4426950408889634f
#define SCALE 16.0f
#define SINV (2.0f * L2E / (SCALE * SCALE))

// ---------------- scratch (chunk-major, PRE-SWIZZLED) ----------------
__device__ uint8_t g_phi8[Kn * Dn];
__device__ uint8_t g_x8[Bn * Dn];
__device__ float g_phinorm[Kn];
__device__ float g_xnorm[Bn];
__device__ float g_colsum[Bn];
__device__ int   g_cnt[Bn / NTILE];

// ---------------- helpers ----------------
__device__ __forceinline__ uint32_t smem_u32(const void* p) {
    uint32_t a;
    asm("{ .reg .u64 t; cvta.to.shared.u64 t, %1; cvt.u32.u64 %0, t; }" : "=r"(a) : "l"(p));
    return a;
}

#define LDSM4(r0, r1, r2, r3, addr) \
    asm volatile("ldmatrix.sync.aligned.m8n8.x4.shared.b16 {%0,%1,%2,%3}, [%4];" \
                 : "=r"(r0), "=r"(r1), "=r"(r2), "=r"(r3) : "r"(addr))

#define MMA16832(d, a, b0, b1) \
    asm volatile("mma.sync.aligned.m16n8k32.row.col.f32.e4m3.e4m3.f32 " \
                 "{%0,%1,%2,%3}, {%4,%5,%6,%7}, {%8,%9}, {%0,%1,%2,%3};" \
                 : "+f"((d)[0]), "+f"((d)[1]), "+f"((d)[2]), "+f"((d)[3]) \
                 : "r"((a)[0]), "r"((a)[1]), "r"((a)[2]), "r"((a)[3]), \
                   "r"(b0), "r"(b1))

#define MBARRIER_INIT(mb, cnt) \
    asm volatile("mbarrier.init.shared.b64 [%0], %1;" :: "r"(mb), "r"(cnt) : "memory")
#define MBARRIER_EXPECT_TX(mb, bytes) \
    asm volatile("mbarrier.arrive.expect_tx.shared.b64 _, [%0], %1;" :: "r"(mb), "r"(bytes) : "memory")
#define MBARRIER_WAIT_PARITY(mb, ph) do {                                        \
    uint32_t _m = (mb); uint32_t _p = (ph); uint32_t _done;                      \
    asm volatile("{\n\t.reg .pred p;\n\t"                                        \
        "mbarrier.try_wait.parity.shared.b64 p, [%1], %2;\n\t"                   \
        "selp.b32 %0, 1, 0, p;\n\t}" : "=r"(_done) : "r"(_m), "r"(_p) : "memory");\
    if (!_done) {                                                                \
        asm volatile("{\n\t.reg .pred P1;\n\t"                                   \
        "WL_%=:\n\t"                                                             \
        "mbarrier.try_wait.parity.shared.b64 P1, [%0], %1;\n\t"                  \
        "@P1 bra.uni WD_%=;\n\t"                                                 \
        "bra.uni WL_%=;\n\t"                                                     \
        "WD_%=:\n\t}" :: "r"(_m), "r"(_p) : "memory");                           \
    }                                                                            \
} while (0)

__device__ __forceinline__ void bulk_cp(uint32_t dst, const void* src,
                                        uint32_t bytes, uint32_t mbar) {
    asm volatile(
        "cp.async.bulk.shared::cluster.global.mbarrier::complete_tx::bytes "
        "[%0], [%1], %2, [%3];"
        :: "r"(dst), "l"(src), "r"(bytes), "r"(mbar) : "memory");
}

__device__ __forceinline__ uint32_t pack_e4m3x4(float e0, float e1, float e2, float e3) {
    uint16_t lo, hi;
    asm("cvt.rn.satfinite.e4m3x2.f32 %0, %1, %2;" : "=h"(lo) : "f"(e1), "f"(e0));
    asm("cvt.rn.satfinite.e4m3x2.f32 %0, %1, %2;" : "=h"(hi) : "f"(e3), "f"(e2));
    return (uint32_t)lo | ((uint32_t)hi << 16);
}

// fast 2^t, FFMA-only. deg-4 poly on [-0.5, 0.5]
__device__ __forceinline__ float exp2_fast(float t) {
    t = fmaxf(t, -126.0f);
    const int   i = __float2int_rn(t);
    const float f = t - (float)i;
    float p = fmaf(0.0096181291f, f, 0.0555041087f);
    p = fmaf(p, f, 0.2402265069f);
    p = fmaf(p, f, 0.6931471806f);
    p = fmaf(p, f, 1.0f);
    return p * __int_as_float((i + 127) << 23);
}

// ============================================================
// Kernel 1 (prep): blocks [0, 2048) = x (warp per row);
//                  blocks [2048, 2048+Kn) = phi MLP
// Both write CHUNK-MAJOR PRE-SWIZZLED fp8.
// ============================================================
__global__ __launch_bounds__(256) void prep_kernel(
    const float* __restrict__ x,  const float* __restrict__ z,
    const float* __restrict__ W1, const float* __restrict__ b1,
    const float* __restrict__ W2, const float* __restrict__ b2,
    float* __restrict__ out)
{
    const int t = threadIdx.x;

    if (blockIdx.x < Bn / 8) {
        const int lane = t & 31;
        const int b = blockIdx.x * 8 + (t >> 5);
        const float* xr = x + (uint64_t)b * Dn;
        const uint32_t rowoff = ((((lane >> 2) ^ (b & 7)) << 4) | ((lane & 3) << 2));
        uint8_t* xo = g_x8 + (uint64_t)b * 128 + rowoff;
        float nrm = 0.0f;
        #pragma unroll
        for (int i = 0; i < 8; i++) {
            const float4 v = *reinterpret_cast<const float4*>(xr + i * 128 + lane * 4);
            *reinterpret_cast<uint32_t*>(xo + i * CHB_X) =
                pack_e4m3x4(v.x * SCALE, v.y * SCALE, v.z * SCALE, v.w * SCALE);
            nrm = fmaf(v.x, v.x, nrm);
            nrm = fmaf(v.y, v.y, nrm);
            nrm = fmaf(v.z, v.z, nrm);
            nrm = fmaf(v.w, v.w, nrm);
        }
        #pragma unroll
        for (int off = 16; off > 0; off >>= 1)
            nrm += __shfl_xor_sync(0xffffffffu, nrm, off);
        if (lane == 0) {
            g_xnorm[b] = nrm;
            g_colsum[b] = 0.0f;
            if (b < Bn / NTILE) g_cnt[b] = 0;
            if (b == 0) out[0] = 0.0f;
        }
    } else {
        __shared__ float zrow[Ln];
        __shared__ float hidden[Hn];
        __shared__ float red[256];
        const int k = blockIdx.x - Bn / 8;

        if (t < Ln) zrow[t] = z[k * Ln + t];
        __syncthreads();

        if (t < Hn) {
            float acc = b1[t];
            #pragma unroll 8
            for (int l = 0; l < Ln; l++)
                acc = fmaf(zrow[l], W1[l * Hn + t], acc);
            hidden[t] = fmaxf(acc, 0.0f);
        }
        __syncthreads();

        const int d0 = t * 4;
        float4 acc = make_float4(b2[d0], b2[d0 + 1], b2[d0 + 2], b2[d0 + 3]);
        #pragma unroll 8
        for (int h = 0; h < Hn; h++) {
            const float hv = hidden[h];
            const float4 w = *reinterpret_cast<const float4*>(W2 + h * Dn + d0);
            acc.x = fmaf(hv, w.x, acc.x);
            acc.y = fmaf(hv, w.y, acc.y);
            acc.z = fmaf(hv, w.z, acc.z);
            acc.w = fmaf(hv, w.w, acc.w);
        }
        {
            const int chunk = t >> 5;
            const uint32_t rowoff = (((((t >> 2) & 7) ^ (k & 7)) << 4) | ((t & 3) << 2));
            *reinterpret_cast<uint32_t*>(
                g_phi8 + (uint64_t)chunk * CHB_PHI + (uint64_t)k * 128 + rowoff) =
                pack_e4m3x4(acc.x * SCALE, acc.y * SCALE, acc.z * SCALE, acc.w * SCALE);
        }

        red[t] = acc.x * acc.x + acc.y * acc.y + acc.z * acc.z + acc.w * acc.w;
        __syncthreads();
        for (int s = 128; s > 0; s >>= 1) {
            if (t < s) red[t] += red[t + s];
            __syncthreads();
        }
        if (t == 0) g_phinorm[k] = red[0];
    }
}

// ============================================================
// Kernel 2 (main): fp8 mma GEMM 128x128; bulk-TMA (cp.async.bulk)
//   staging of contiguous pre-swizzled 16KB tiles; fused exp epilogue
// ============================================================
__global__ __launch_bounds__(256, 2) void main_kernel(float* __restrict__ out)
{
    extern __shared__ char smem[];
    const uint32_t Sal = (smem_u32(smem) + 127u) & ~127u;
    const uint32_t MB  = Sal + OFF_MBAR;        // 3 mbarriers (8B each)

    const int t    = threadIdx.x;
    const int lane = t & 31;
    const int wid  = t >> 5;
    const int b_base = blockIdx.x * NTILE;
    const int k_base = blockIdx.y * MTILE;

    const int m_off = (wid & 1) * 64;
    const int n_off = (wid >> 1) * 32;

    const uint8_t* srcA = g_phi8 + (uint64_t)k_base * 128;   // +c*CHB_PHI, 16KB
    const uint8_t* srcB = g_x8   + (uint64_t)b_base * 128;   // +c*CHB_X,   16KB

    // ---- init mbarriers ----
    if (t == 0) {
        MBARRIER_INIT(MB + 0,  1);
        MBARRIER_INIT(MB + 8,  1);
        MBARRIER_INIT(MB + 16, 1);
        asm volatile("fence.proxy.async.shared::cta;" ::: "memory");
    }
    __syncthreads();

    // ---- prologue: stage chunks 0, 1 ----
    if (t == 0) {
        #pragma unroll
        for (int pc = 0; pc < 2; pc++) {
            const uint32_t st = Sal + (uint32_t)pc * STAGE_BYTES;
            MBARRIER_EXPECT_TX(MB + pc * 8, STAGE_BYTES);
            bulk_cp(st,          srcA + (uint64_t)pc * CHB_PHI, 16384u, MB + pc * 8);
            bulk_cp(st + 16384u, srcB + (uint64_t)pc * CHB_X,   16384u, MB + pc * 8);
        }
    }

    // ---- loop-invariant LDSM base offsets (within a stage) ----
    uint32_t a_base[4], b_base2[2];
    {
        const int hi = lane >> 4;
        #pragma unroll
        for (int im = 0; im < 4; im++) {
            const int arow = m_off + im * 16 + (lane & 15);
            const int r = arow & 7;
            a_base[im] = (uint32_t)(arow * 128 + ((hi ^ (r & 1)) << 4) + ((r & 6) << 4));
        }
        const int g  = lane >> 3;
        const int rb = lane & 7;
        #pragma unroll
        for (int in_ = 0; in_ < 2; in_++) {
            const int nrow = n_off + in_ * 16 + ((g >> 1) << 3) + rb;
            b_base2[in_] = (uint32_t)(nrow * 128 + (((g & 1) ^ (rb & 1)) << 4) + ((rb & 6) << 4));
        }
    }

    float acc[4][4][4];
    #pragma unroll
    for (int i = 0; i < 4; i++)
        #pragma unroll
        for (int j = 0; j < 4; j++)
            #pragma unroll
            for (int r = 0; r < 4; r++) acc[i][j][r] = 0.0f;

    int ph0 = 0, ph1 = 0, ph2 = 0;

    for (int c = 0; c < NCHUNK; c++) {
        const int s = c % STAGES;
        if (s == 0)      { MBARRIER_WAIT_PARITY(MB + 0,  (uint32_t)ph0); ph0 ^= 1; }
        else if (s == 1) { MBARRIER_WAIT_PARITY(MB + 8,  (uint32_t)ph1); ph1 ^= 1; }
        else             { MBARRIER_WAIT_PARITY(MB + 16, (uint32_t)ph2); ph2 ^= 1; }
        __syncthreads();   // all warps past stage (c+2)%3's consumption

        if (c + 2 < NCHUNK && t == 0) {
            const int sn_ = (c + 2) % STAGES;
            const uint32_t st = Sal + (uint32_t)sn_ * STAGE_BYTES;
            MBARRIER_EXPECT_TX(MB + sn_ * 8, STAGE_BYTES);
            bulk_cp(st,          srcA + (uint64_t)(c + 2) * CHB_PHI, 16384u, MB + sn_ * 8);
            bulk_cp(st + 16384u, srcB + (uint64_t)(c + 2) * CHB_X,   16384u, MB + sn_ * 8);
        }

        const uint32_t As = Sal + (uint32_t)s * STAGE_BYTES;
        uint32_t aaddr[4], baddr[2];
        #pragma unroll
        for (int im = 0; im < 4; im++) aaddr[im] = As + a_base[im];
        #pragma unroll
        for (int in_ = 0; in_ < 2; in_++) baddr[in_] = As + 16384u + b_base2[in_];

        #pragma unroll
        for (int ks = 0; ks < 4; ks++) {
            const uint32_t kx = (uint32_t)ks << 5;
            uint32_t a[4][4];
            #pragma unroll
            for (int im = 0; im < 4; im++)
                LDSM4(a[im][0], a[im][1], a[im][2], a[im][3], aaddr[im] ^ kx);
            uint32_t b[8];
            #pragma unroll
            for (int in_ = 0; in_ < 2; in_++)
                LDSM4(b[in_ * 4 + 0], b[in_ * 4 + 1], b[in_ * 4 + 2], b[in_ * 4 + 3],
                      baddr[in_] ^ kx);
            #pragma unroll
            for (int im = 0; im < 4; im++)
                #pragma unroll
                for (int ing = 0; ing < 4; ing++)
                    MMA16832(acc[im][ing], a[im], b[ing * 2], b[ing * 2 + 1]);
        }
    }

    // ---------------- fused epilogue ----------------
    float pnl[4], pnh[4];
    #pragma unroll
    for (int im = 0; im < 4; im++) {
        pnl[im] = g_phinorm[k_base + m_off + im * 16 + (lane >> 2)] * L2E;
        pnh[im] = g_phinorm[k_base + m_off + im * 16 + (lane >> 2) + 8] * L2E;
    }
    float xnv[4][2];
    #pragma unroll
    for (int ing = 0; ing < 4; ing++)
        #pragma unroll
        for (int j = 0; j < 2; j++)
            xnv[ing][j] = g_xnorm[b_base + n_off + ing * 8 + (lane & 3) * 2 + j] * L2E;

    float sn[4][2];
    #pragma unroll
    for (int ing = 0; ing < 4; ing++) { sn[ing][0] = 0.0f; sn[ing][1] = 0.0f; }

    #pragma unroll
    for (int im = 0; im < 4; im++) {
        #pragma unroll
        for (int ing = 0; ing < 4; ing++) {
            #pragma unroll
            for (int j = 0; j < 2; j++) {
                sn[ing][j] += exp2_fast(fmaf(SINV, acc[im][ing][j],     -(pnl[im] + xnv[ing][j])));
                sn[ing][j] += exp2_fast(fmaf(SINV, acc[im][ing][2 + j], -(pnh[im] + xnv[ing][j])));
            }
        }
    }
    #pragma unroll
    for (int off = 4; off < 32; off <<= 1)
        #pragma unroll
        for (int ing = 0; ing < 4; ing++)
            #pragma unroll
            for (int j = 0; j < 2; j++)
                sn[ing][j] += __shfl_xor_sync(0xffffffffu, sn[ing][j], off);

    if (lane < 4) {
        #pragma unroll
        for (int ing = 0; ing < 4; ing++)
            #pragma unroll
            for (int j = 0; j < 2; j++)
                atomicAdd(&g_colsum[b_base + n_off + ing * 8 + lane * 2 + j], sn[ing][j]);
    }

    // ---- last CTA of this b-slice finalizes its 128 columns ----
    __shared__ int is_last;
    __threadfence();
    if (t == 0) {
        const int old = atomicAdd(&g_cnt[blockIdx.x], 1);
        is_last = (old == (Kn / MTILE) - 1);
    }
    __syncthreads();
    if (is_last && t < NTILE) {
        float s = __logf(g_colsum[b_base + t] * (1.0f / (float)Kn) + 1e-9f)
                  * (1.0f / (float)Bn);
        #pragma unroll
        for (int off = 16; off > 0; off >>= 1)
            s += __shfl_xor_sync(0xffffffffu, s, off);
        if (lane == 0) atomicAdd(out, s);
    }
}

// ============================================================
extern "C" void kernel_launch(void* const* d_in, const int* in_sizes, int n_in,
                              void* d_out, int out_size)
{
    const float* x  = (const float*)d_in[0];
    const float* z  = (const float*)d_in[1];
    const float* W1 = (const float*)d_in[2];
    const float* b1 = (const float*)d_in[3];
    const float* W2 = (const float*)d_in[4];
    const float* b2 = (const float*)d_in[5];
    float* out = (float*)d_out;

    static int smem_set = 0;
    if (!smem_set) {
        cudaFuncSetAttribute(main_kernel, cudaFuncAttributeMaxDynamicSharedMemorySize,
                             SMEM_REQ);
        smem_set = 1;
    }

    prep_kernel<<<Bn / 8 + Kn, 256>>>(x, z, W1, b1, W2, b2, out);
    dim3 grid(Bn / NTILE, Kn / MTILE);   // (128, 4)
    main_kernel<<<grid, 256, SMEM_REQ>>>(out);
}